// round 7
// baseline (speedup 1.0000x reference)
#include <cuda_runtime.h>
#include <cuda_bf16.h>
#include <cstdint>

// ---- problem dims ----------------------------------------------------------
#define BV 16                      // B*V
#define ROWS_PER_BV 65536          // T*N*D
#define Mq 128                     // rows per block
#define Nq 64                      // F_OUT
#define Kq 64                      // F_IN
#define Rq 16
#define RVq 4
#define TPB 128

// Precomputed B fragments, mma.m16n8k16 register layout, hi/lo packed:
// [bv][kt(4)][nt(8)][lane(32)] -> uint4 {bh0, bh1, bl0, bl1}
__device__ __align__(16) uint4 g_Bf[BV * 4 * 8 * 32];

__device__ __forceinline__ uint32_t pack_bf16x2(float lo, float hi) {
    __nv_bfloat16 l = __float2bfloat16(lo), h = __float2bfloat16(hi);
    return ((uint32_t)__bfloat16_as_ushort(h) << 16) | __bfloat16_as_ushort(l);
}

// split a float2 into packed bf16x2 hi + lo (error-compensated)
__device__ __forceinline__ void split2(float2 v, uint32_t& h, uint32_t& l) {
    __nv_bfloat16 hx = __float2bfloat16(v.x), hy = __float2bfloat16(v.y);
    float fx = __bfloat162float(hx), fy = __bfloat162float(hy);
    h = ((uint32_t)__bfloat16_as_ushort(hy) << 16) | __bfloat16_as_ushort(hx);
    l = pack_bf16x2(v.x - fx, v.y - fy);
}

__device__ __forceinline__ void mma_bf16(float* c, const uint32_t* a,
                                         uint32_t b0, uint32_t b1) {
    asm volatile(
        "mma.sync.aligned.m16n8k16.row.col.f32.bf16.bf16.f32 "
        "{%0,%1,%2,%3}, {%4,%5,%6,%7}, {%8,%9}, {%0,%1,%2,%3};"
        : "+f"(c[0]), "+f"(c[1]), "+f"(c[2]), "+f"(c[3])
        : "r"(a[0]), "r"(a[1]), "r"(a[2]), "r"(a[3]), "r"(b0), "r"(b1));
}

// ---- precompute: W[bv] -> bf16 hi/lo B-fragments ---------------------------
__global__ void precompute_kernel(const int* __restrict__ var_idx,
                                  const float* __restrict__ core,        // (RV, R, R)
                                  const float* __restrict__ factor_vars, // (NVAR, RV)
                                  const float* __restrict__ fac_in,      // (R, 64)
                                  const float* __restrict__ fac_out) {   // (R, 64)
    int bv = blockIdx.x;
    int e  = threadIdx.x;      // 0..63  (output column n = e)
    __shared__ float fvs[RVq];
    __shared__ float ceff[Rq * Rq];

    if (e < RVq) fvs[e] = factor_vars[var_idx[bv] * RVq + e];
    __syncthreads();
    for (int i = e; i < Rq * Rq; i += 64) {
        float s = 0.f;
        #pragma unroll
        for (int A = 0; A < RVq; ++A) s += fvs[A] * core[A * Rq * Rq + i];
        ceff[i] = s;
    }
    __syncthreads();

    float H[Rq];
    #pragma unroll
    for (int r = 0; r < Rq; ++r) {
        float s = 0.f;
        #pragma unroll
        for (int c = 0; c < Rq; ++c) s += ceff[r * Rq + c] * fac_out[c * Nq + e];
        H[r] = s;
    }
    // Wcol[a] = W[a][e] = sum_r fac_in[r][a] * H[r], split hi/lo
    float Wh[Kq], Wl[Kq];
    for (int a = 0; a < Kq; ++a) {
        float s = 0.f;
        #pragma unroll
        for (int r = 0; r < Rq; ++r) s += fac_in[r * Kq + a] * H[r];
        float hi = __bfloat162float(__float2bfloat16(s));
        Wh[a] = hi;
        Wl[a] = s - hi;
    }
    // fragment layout: col n=e -> nt=e>>3, lanes (e&7)*4 + tig, k0 = 16*kt + 2*tig
    int nt = e >> 3, c4 = (e & 7) * 4;
    #pragma unroll
    for (int kt = 0; kt < 4; ++kt) {
        #pragma unroll
        for (int tig = 0; tig < 4; ++tig) {
            int lane = c4 + tig;
            int k0 = 16 * kt + 2 * tig;
            int idx = ((bv * 4 + kt) * 8 + nt) * 32 + lane;
            g_Bf[idx] = make_uint4(pack_bf16x2(Wh[k0],     Wh[k0 + 1]),
                                   pack_bf16x2(Wh[k0 + 8], Wh[k0 + 9]),
                                   pack_bf16x2(Wl[k0],     Wl[k0 + 1]),
                                   pack_bf16x2(Wl[k0 + 8], Wl[k0 + 9]));
        }
    }
}

// ---- main kernel -----------------------------------------------------------
__global__ void __launch_bounds__(TPB, 4)
tucker_mma_kernel(const float* __restrict__ x, float* __restrict__ out) {
    __shared__ uint4 sB[4 * 8 * 32];     // 16 KB: packed B fragments

    const int bv   = blockIdx.y;
    const int t    = threadIdx.x;
    const int w    = t >> 5, lane = t & 31;
    const size_t base = ((size_t)bv * ROWS_PER_BV + (size_t)blockIdx.x * Mq) * (size_t)Kq;

    // stage B fragments: 16 KB, 8 x (LDG.128 -> STS.128) per thread
    {
        const uint4* gb = g_Bf + bv * 1024;
        #pragma unroll
        for (int it = 0; it < 8; ++it) {
            int i = it * TPB + t;
            sB[i] = gb[i];
        }
    }
    __syncthreads();

    // accumulators: 2 m-tiles x 8 n-tiles x 4 floats
    float acc[2][8][4];
    #pragma unroll
    for (int mt = 0; mt < 2; ++mt)
        #pragma unroll
        for (int nt = 0; nt < 8; ++nt)
            #pragma unroll
            for (int q = 0; q < 4; ++q) acc[mt][nt][q] = 0.f;

    // A fragment coordinates for this lane (direct global loads, sector-perfect):
    // row = w*32 + mt*16 + (lane>>2) (+8), col = kt*16 + (lane&3)*2 (+8)
    const float* xp = x + base;
    const int ar = w * 32 + (lane >> 2);
    const int kc = (lane & 3) * 2;

    #pragma unroll
    for (int kt = 0; kt < 4; ++kt) {
        // B fragments for this k-tile (one LDS.128 per nt, conflict-free)
        uint4 bf[8];
        #pragma unroll
        for (int nt = 0; nt < 8; ++nt)
            bf[nt] = sB[(kt * 8 + nt) * 32 + lane];

        #pragma unroll
        for (int mt = 0; mt < 2; ++mt) {
            const float* r0 = xp + (size_t)(ar + mt * 16) * Kq + kt * 16 + kc;
            const float* r1 = r0 + 8 * Kq;
            float2 p00 = *(const float2*)(r0);
            float2 p01 = *(const float2*)(r0 + 8);
            float2 p10 = *(const float2*)(r1);
            float2 p11 = *(const float2*)(r1 + 8);

            uint32_t ah[4], al[4];
            split2(p00, ah[0], al[0]);
            split2(p10, ah[1], al[1]);
            split2(p01, ah[2], al[2]);
            split2(p11, ah[3], al[3]);

            #pragma unroll
            for (int nt = 0; nt < 8; ++nt) {
                mma_bf16(acc[mt][nt], ah, bf[nt].x, bf[nt].y);   // xh * Wh
                mma_bf16(acc[mt][nt], ah, bf[nt].z, bf[nt].w);   // xh * Wl
                mma_bf16(acc[mt][nt], al, bf[nt].x, bf[nt].y);   // xl * Wh
            }
        }
    }

    // epilogue: direct stores. rows w*32 + mt*16 + (lane>>2) (+8), cols nt*8+(lane&3)*2
    {
        float* ob = out + base;
        const int r0 = w * 32 + (lane >> 2);
        const int cc = (lane & 3) * 2;
        #pragma unroll
        for (int mt = 0; mt < 2; ++mt) {
            float* p0 = ob + (size_t)(r0 + mt * 16) * Nq + cc;
            float* p1 = p0 + 8 * Nq;
            #pragma unroll
            for (int nt = 0; nt < 8; ++nt) {
                *(float2*)(p0 + nt * 8) = make_float2(acc[mt][nt][0], acc[mt][nt][1]);
                *(float2*)(p1 + nt * 8) = make_float2(acc[mt][nt][2], acc[mt][nt][3]);
            }
        }
    }
}

extern "C" void kernel_launch(void* const* d_in, const int* in_sizes, int n_in,
                              void* d_out, int out_size) {
    const float* x           = (const float*)d_in[0];
    const int*   var_idx     = (const int*)d_in[1];
    const float* core        = (const float*)d_in[2];
    const float* factor_vars = (const float*)d_in[3];
    const float* fac_in      = (const float*)d_in[4];
    const float* fac_out     = (const float*)d_in[5];
    float* out = (float*)d_out;

    precompute_kernel<<<BV, 64>>>(var_idx, core, factor_vars, fac_in, fac_out);

    dim3 grid(ROWS_PER_BV / Mq, BV);   // (512, 16)
    tucker_mma_kernel<<<grid, TPB>>>(x, out);
}

// round 8
// speedup vs baseline: 1.1428x; 1.1428x over previous
#include <cuda_runtime.h>
#include <cuda_bf16.h>
#include <cstdint>

// ---- problem dims ----------------------------------------------------------
#define BV 16                      // B*V
#define ROWS_PER_BV 65536          // T*N*D
#define Mq 128                     // rows per block
#define Nq 64                      // F_OUT
#define Kq 64                      // F_IN
#define Rq 16
#define RVq 4
#define TPB 256                    // 8 warps x 16 rows

#define SWZ(o) ((o) ^ (((o) >> 3) & 0x70))

// Precomputed B fragments, mma.m16n8k16 register layout, hi/lo packed:
// [bv][kt(4)][nt(8)][lane(32)] -> uint4 {bh0, bh1, bl0, bl1}
__device__ __align__(16) uint4 g_Bf[BV * 4 * 8 * 32];

__device__ __forceinline__ uint32_t smem_u32(const void* p) {
    uint32_t a;
    asm("{ .reg .u64 t; cvta.to.shared.u64 t, %1; cvt.u32.u64 %0, t; }" : "=r"(a) : "l"(p));
    return a;
}

__device__ __forceinline__ uint32_t pack_bf16x2(float lo, float hi) {
    __nv_bfloat16 l = __float2bfloat16(lo), h = __float2bfloat16(hi);
    return ((uint32_t)__bfloat16_as_ushort(h) << 16) | __bfloat16_as_ushort(l);
}

__device__ __forceinline__ void ldmatrix_x4(uint32_t& r0, uint32_t& r1,
                                            uint32_t& r2, uint32_t& r3, uint32_t addr) {
    asm volatile("ldmatrix.sync.aligned.m8n8.x4.shared.b16 {%0,%1,%2,%3}, [%4];"
                 : "=r"(r0), "=r"(r1), "=r"(r2), "=r"(r3) : "r"(addr));
}

__device__ __forceinline__ void mma_bf16(float* c, const uint32_t* a,
                                         uint32_t b0, uint32_t b1) {
    asm volatile(
        "mma.sync.aligned.m16n8k16.row.col.f32.bf16.bf16.f32 "
        "{%0,%1,%2,%3}, {%4,%5,%6,%7}, {%8,%9}, {%0,%1,%2,%3};"
        : "+f"(c[0]), "+f"(c[1]), "+f"(c[2]), "+f"(c[3])
        : "r"(a[0]), "r"(a[1]), "r"(a[2]), "r"(a[3]), "r"(b0), "r"(b1));
}

// ---- precompute: W[bv] -> bf16 hi/lo B-fragments ---------------------------
__global__ void precompute_kernel(const int* __restrict__ var_idx,
                                  const float* __restrict__ core,        // (RV, R, R)
                                  const float* __restrict__ factor_vars, // (NVAR, RV)
                                  const float* __restrict__ fac_in,      // (R, 64)
                                  const float* __restrict__ fac_out) {   // (R, 64)
    int bv = blockIdx.x;
    int e  = threadIdx.x;      // 0..63  (output column n = e)
    __shared__ float fvs[RVq];
    __shared__ float ceff[Rq * Rq];

    if (e < RVq) fvs[e] = factor_vars[var_idx[bv] * RVq + e];
    __syncthreads();
    for (int i = e; i < Rq * Rq; i += 64) {
        float s = 0.f;
        #pragma unroll
        for (int A = 0; A < RVq; ++A) s += fvs[A] * core[A * Rq * Rq + i];
        ceff[i] = s;
    }
    __syncthreads();

    float H[Rq];
    #pragma unroll
    for (int r = 0; r < Rq; ++r) {
        float s = 0.f;
        #pragma unroll
        for (int c = 0; c < Rq; ++c) s += ceff[r * Rq + c] * fac_out[c * Nq + e];
        H[r] = s;
    }
    // Wcol[a] = W[a][e] = sum_r fac_in[r][a] * H[r], split hi/lo
    float Wh[Kq], Wl[Kq];
    for (int a = 0; a < Kq; ++a) {
        float s = 0.f;
        #pragma unroll
        for (int r = 0; r < Rq; ++r) s += fac_in[r * Kq + a] * H[r];
        float hi = __bfloat162float(__float2bfloat16(s));
        Wh[a] = hi;
        Wl[a] = s - hi;
    }
    // fragment layout: col n=e -> nt=e>>3, lanes (e&7)*4 + tig, k0 = 16*kt + 2*tig
    int nt = e >> 3, c4 = (e & 7) * 4;
    #pragma unroll
    for (int kt = 0; kt < 4; ++kt) {
        #pragma unroll
        for (int tig = 0; tig < 4; ++tig) {
            int lane = c4 + tig;
            int k0 = 16 * kt + 2 * tig;
            int idx = ((bv * 4 + kt) * 8 + nt) * 32 + lane;
            g_Bf[idx] = make_uint4(pack_bf16x2(Wh[k0],     Wh[k0 + 1]),
                                   pack_bf16x2(Wh[k0 + 8], Wh[k0 + 9]),
                                   pack_bf16x2(Wl[k0],     Wl[k0 + 1]),
                                   pack_bf16x2(Wl[k0 + 8], Wl[k0 + 9]));
        }
    }
}

// ---- main kernel: 8 warps x 16 rows, smem-staged A + ldmatrix --------------
__global__ void __launch_bounds__(TPB, 3)
tucker_mma_kernel(const float* __restrict__ x, float* __restrict__ out) {
    __shared__ __align__(1024) char sAH[Mq * 128];   // 16 KB bf16 hi, 128B rows, SW128
    __shared__ __align__(1024) char sAL[Mq * 128];   // 16 KB bf16 lo
    __shared__ __align__(16) uint4 sB[4 * 8 * 32];   // 16 KB packed B fragments

    const int bv   = blockIdx.y;
    const int t    = threadIdx.x;
    const int w    = t >> 5, lane = t & 31;
    const size_t base = ((size_t)bv * ROWS_PER_BV + (size_t)blockIdx.x * Mq) * (size_t)Kq;

    // stage B fragments: 4 x (LDG.128 -> STS.128) per thread
    {
        const uint4* gb = g_Bf + bv * 1024;
        #pragma unroll
        for (int it = 0; it < 4; ++it) {
            int i = it * TPB + t;
            sB[i] = gb[i];
        }
    }

    // stage A: fp32 -> bf16 hi/lo, swizzled 128B rows; 8 x LDG.128 per thread
    {
        const float4* gx = (const float4*)(x + base);
        #pragma unroll
        for (int it = 0; it < 8; ++it) {
            int i = it * TPB + t;                        // float4 id: row=i>>4, c4=i&15
            float4 v = gx[i];
            float h0 = __bfloat162float(__float2bfloat16(v.x));
            float h1 = __bfloat162float(__float2bfloat16(v.y));
            float h2 = __bfloat162float(__float2bfloat16(v.z));
            float h3 = __bfloat162float(__float2bfloat16(v.w));
            uint32_t hiA = pack_bf16x2(h0, h1);
            uint32_t hiB = pack_bf16x2(h2, h3);
            uint32_t loA = pack_bf16x2(v.x - h0, v.y - h1);
            uint32_t loB = pack_bf16x2(v.z - h2, v.w - h3);
            uint32_t off = SWZ((uint32_t)((i >> 4) * 128 + (i & 15) * 8));
            *(uint2*)(sAH + off) = make_uint2(hiA, hiB);
            *(uint2*)(sAL + off) = make_uint2(loA, loB);
        }
    }
    __syncthreads();

    // accumulators: 1 m-tile x 8 n-tiles x 4 floats
    float acc[8][4];
    #pragma unroll
    for (int nt = 0; nt < 8; ++nt)
        #pragma unroll
        for (int q = 0; q < 4; ++q) acc[nt][q] = 0.f;

    // ldmatrix address: row = w*16 + (lane&15), kbyte = kt*32 + (lane>>4)*16
    const uint32_t sbAH = smem_u32(sAH), sbAL = smem_u32(sAL);
    const int arow = w * 16 + (lane & 15);
    const int koff = (lane >> 4) * 16;

    #pragma unroll
    for (int kt = 0; kt < 4; ++kt) {
        uint32_t ah[4], al[4];
        uint32_t off = SWZ((uint32_t)(arow * 128 + kt * 32 + koff));
        ldmatrix_x4(ah[0], ah[1], ah[2], ah[3], sbAH + off);
        ldmatrix_x4(al[0], al[1], al[2], al[3], sbAL + off);

        #pragma unroll
        for (int ng = 0; ng < 2; ++ng) {                 // nt chunks of 4 (reg cap)
            uint4 bf[4];
            #pragma unroll
            for (int j = 0; j < 4; ++j)
                bf[j] = sB[(kt * 8 + ng * 4 + j) * 32 + lane];
            #pragma unroll
            for (int j = 0; j < 4; ++j) {
                float* c = acc[ng * 4 + j];
                mma_bf16(c, ah, bf[j].x, bf[j].y);       // xh * Wh
                mma_bf16(c, ah, bf[j].z, bf[j].w);       // xh * Wl
                mma_bf16(c, al, bf[j].x, bf[j].y);       // xl * Wh
            }
        }
    }

    // epilogue: direct stores. rows w*16 + (lane>>2) (+8), cols nt*8 + (lane&3)*2
    {
        float* ob = out + base;
        const int r0 = w * 16 + (lane >> 2);
        const int cc = (lane & 3) * 2;
        float* p0 = ob + (size_t)r0 * Nq + cc;
        float* p1 = p0 + 8 * Nq;
        #pragma unroll
        for (int nt = 0; nt < 8; ++nt) {
            *(float2*)(p0 + nt * 8) = make_float2(acc[nt][0], acc[nt][1]);
            *(float2*)(p1 + nt * 8) = make_float2(acc[nt][2], acc[nt][3]);
        }
    }
}

extern "C" void kernel_launch(void* const* d_in, const int* in_sizes, int n_in,
                              void* d_out, int out_size) {
    const float* x           = (const float*)d_in[0];
    const int*   var_idx     = (const int*)d_in[1];
    const float* core        = (const float*)d_in[2];
    const float* factor_vars = (const float*)d_in[3];
    const float* fac_in      = (const float*)d_in[4];
    const float* fac_out     = (const float*)d_in[5];
    float* out = (float*)d_out;

    precompute_kernel<<<BV, 64>>>(var_idx, core, factor_vars, fac_in, fac_out);

    dim3 grid(ROWS_PER_BV / Mq, BV);   // (512, 16)
    tucker_mma_kernel<<<grid, TPB>>>(x, out);
}

// round 9
// speedup vs baseline: 1.2408x; 1.0858x over previous
#include <cuda_runtime.h>
#include <cuda_bf16.h>
#include <cstdint>

// ---- problem dims ----------------------------------------------------------
#define BV 16                      // B*V
#define ROWS_PER_BV 65536          // T*N*D
#define Mq 128                     // rows per block
#define Nq 64                      // F_OUT
#define Kq 64                      // F_IN
#define Rq 16
#define RVq 4
#define TPB 256                    // 8 warps: 4 row-groups x 2 n-halves

#define SWZ(o) ((o) ^ (((o) >> 3) & 0x70))

// Precomputed B fragments, mma.m16n8k16 register layout, hi/lo packed:
// [bv][kt(4)][nt(8)][lane(32)] -> uint4 {bh0, bh1, bl0, bl1}
__device__ __align__(16) uint4 g_Bf[BV * 4 * 8 * 32];

__device__ __forceinline__ uint32_t smem_u32(const void* p) {
    uint32_t a;
    asm("{ .reg .u64 t; cvta.to.shared.u64 t, %1; cvt.u32.u64 %0, t; }" : "=r"(a) : "l"(p));
    return a;
}

__device__ __forceinline__ uint32_t pack_bf16x2(float lo, float hi) {
    __nv_bfloat16 l = __float2bfloat16(lo), h = __float2bfloat16(hi);
    return ((uint32_t)__bfloat16_as_ushort(h) << 16) | __bfloat16_as_ushort(l);
}

__device__ __forceinline__ void ldmatrix_x4(uint32_t& r0, uint32_t& r1,
                                            uint32_t& r2, uint32_t& r3, uint32_t addr) {
    asm volatile("ldmatrix.sync.aligned.m8n8.x4.shared.b16 {%0,%1,%2,%3}, [%4];"
                 : "=r"(r0), "=r"(r1), "=r"(r2), "=r"(r3) : "r"(addr));
}

__device__ __forceinline__ void mma_bf16(float* c, const uint32_t* a,
                                         uint32_t b0, uint32_t b1) {
    asm volatile(
        "mma.sync.aligned.m16n8k16.row.col.f32.bf16.bf16.f32 "
        "{%0,%1,%2,%3}, {%4,%5,%6,%7}, {%8,%9}, {%0,%1,%2,%3};"
        : "+f"(c[0]), "+f"(c[1]), "+f"(c[2]), "+f"(c[3])
        : "r"(a[0]), "r"(a[1]), "r"(a[2]), "r"(a[3]), "r"(b0), "r"(b1));
}

// ---- precompute: W[bv] -> bf16 hi/lo B-fragments (parallel over e x kt) ----
__global__ void precompute_kernel(const int* __restrict__ var_idx,
                                  const float* __restrict__ core,        // (RV, R, R)
                                  const float* __restrict__ factor_vars, // (NVAR, RV)
                                  const float* __restrict__ fac_in,      // (R, 64)
                                  const float* __restrict__ fac_out) {   // (R, 64)
    int bv = blockIdx.x;
    int t  = threadIdx.x;      // 0..255
    int e  = t & 63;           // output column
    int kt = t >> 6;           // k-tile 0..3

    __shared__ float fvs[RVq];
    __shared__ float ceff[Rq * Rq];

    if (t < RVq) fvs[t] = factor_vars[var_idx[bv] * RVq + t];
    __syncthreads();
    if (t < Rq * Rq) {
        float s = 0.f;
        #pragma unroll
        for (int A = 0; A < RVq; ++A) s += fvs[A] * core[A * Rq * Rq + t];
        ceff[t] = s;
    }
    __syncthreads();

    float H[Rq];               // H[r] = sum_c Ceff[r][c] * fac_out[c][e]
    #pragma unroll
    for (int r = 0; r < Rq; ++r) {
        float s = 0.f;
        #pragma unroll
        for (int c = 0; c < Rq; ++c) s += ceff[r * Rq + c] * fac_out[c * Nq + e];
        H[r] = s;
    }
    // this thread's 16 a-values: a = 16*kt + j
    float Wh[16], Wl[16];
    #pragma unroll
    for (int j = 0; j < 16; ++j) {
        int a = 16 * kt + j;
        float s = 0.f;
        #pragma unroll
        for (int r = 0; r < Rq; ++r) s += fac_in[r * Kq + a] * H[r];
        float hi = __bfloat162float(__float2bfloat16(s));
        Wh[j] = hi;
        Wl[j] = s - hi;
    }
    // pack fragments: col n=e -> nt=e>>3, lanes (e&7)*4 + tig, local k0 = 2*tig
    int nt = e >> 3, c4 = (e & 7) * 4;
    #pragma unroll
    for (int tig = 0; tig < 4; ++tig) {
        int k0 = 2 * tig;
        int idx = ((bv * 4 + kt) * 8 + nt) * 32 + c4 + tig;
        g_Bf[idx] = make_uint4(pack_bf16x2(Wh[k0],     Wh[k0 + 1]),
                               pack_bf16x2(Wh[k0 + 8], Wh[k0 + 9]),
                               pack_bf16x2(Wl[k0],     Wl[k0 + 1]),
                               pack_bf16x2(Wl[k0 + 8], Wl[k0 + 9]));
    }
}

// ---- main kernel: 8 warps = 4 row-groups (32 rows) x 2 n-halves ------------
__global__ void __launch_bounds__(TPB, 3)
tucker_mma_kernel(const float* __restrict__ x, float* __restrict__ out) {
    __shared__ __align__(1024) char sAH[Mq * 128];   // 16 KB bf16 hi, SW128 rows
    __shared__ __align__(1024) char sAL[Mq * 128];   // 16 KB bf16 lo

    const int bv   = blockIdx.y;
    const int t    = threadIdx.x;
    const int w    = t >> 5, lane = t & 31;
    const int rw   = w & 3;          // row group: rows rw*32 .. rw*32+31
    const int nh   = w >> 2;         // n-half: nt in [nh*4, nh*4+4)
    const size_t base = ((size_t)bv * ROWS_PER_BV + (size_t)blockIdx.x * Mq) * (size_t)Kq;

    // stage A: fp32 -> bf16 hi/lo, swizzled 128B rows; 8 x LDG.128 per thread
    {
        const float4* gx = (const float4*)(x + base);
        #pragma unroll
        for (int it = 0; it < 8; ++it) {
            int i = it * TPB + t;                        // float4 id: row=i>>4, c4=i&15
            float4 v = gx[i];
            float h0 = __bfloat162float(__float2bfloat16(v.x));
            float h1 = __bfloat162float(__float2bfloat16(v.y));
            float h2 = __bfloat162float(__float2bfloat16(v.z));
            float h3 = __bfloat162float(__float2bfloat16(v.w));
            uint32_t hiA = pack_bf16x2(h0, h1);
            uint32_t hiB = pack_bf16x2(h2, h3);
            uint32_t loA = pack_bf16x2(v.x - h0, v.y - h1);
            uint32_t loB = pack_bf16x2(v.z - h2, v.w - h3);
            uint32_t off = SWZ((uint32_t)((i >> 4) * 128 + (i & 15) * 8));
            *(uint2*)(sAH + off) = make_uint2(hiA, hiB);
            *(uint2*)(sAL + off) = make_uint2(loA, loB);
        }
    }
    __syncthreads();

    // accumulators: 2 m-tiles x 4 n-tiles x 4 floats = 32 regs
    float acc[2][4][4];
    #pragma unroll
    for (int mt = 0; mt < 2; ++mt)
        #pragma unroll
        for (int j = 0; j < 4; ++j)
            #pragma unroll
            for (int q = 0; q < 4; ++q) acc[mt][j][q] = 0.f;

    const uint32_t sbAH = smem_u32(sAH), sbAL = smem_u32(sAL);
    const int arow = rw * 32 + (lane & 15);
    const int koff = (lane >> 4) * 16;
    const uint4* gb = g_Bf + (bv * 4 * 8 + nh * 4) * 32 + lane;   // [kt][j] stride

    #pragma unroll
    for (int kt = 0; kt < 4; ++kt) {
        // B fragments for this k-tile / n-half: 4 direct LDG.128 (L1/L2-hot)
        uint4 bf[4];
        #pragma unroll
        for (int j = 0; j < 4; ++j)
            bf[j] = gb[(kt * 8 + j) * 32];

        #pragma unroll
        for (int mt = 0; mt < 2; ++mt) {
            uint32_t ah[4], al[4];
            uint32_t off = SWZ((uint32_t)((arow + mt * 16) * 128 + kt * 32 + koff));
            ldmatrix_x4(ah[0], ah[1], ah[2], ah[3], sbAH + off);
            ldmatrix_x4(al[0], al[1], al[2], al[3], sbAL + off);
            #pragma unroll
            for (int j = 0; j < 4; ++j) {
                float* c = acc[mt][j];
                mma_bf16(c, ah, bf[j].x, bf[j].y);       // xh * Wh
                mma_bf16(c, ah, bf[j].z, bf[j].w);       // xh * Wl
                mma_bf16(c, al, bf[j].x, bf[j].y);       // xl * Wh
            }
        }
    }

    // epilogue: rows rw*32 + mt*16 + (lane>>2) (+8), cols nh*32 + j*8 + (lane&3)*2
    {
        float* ob = out + base;
        const int cc = nh * 32 + (lane & 3) * 2;
        #pragma unroll
        for (int mt = 0; mt < 2; ++mt) {
            const int r0 = rw * 32 + mt * 16 + (lane >> 2);
            float* p0 = ob + (size_t)r0 * Nq + cc;
            float* p1 = p0 + 8 * Nq;
            #pragma unroll
            for (int j = 0; j < 4; ++j) {
                *(float2*)(p0 + j * 8) = make_float2(acc[mt][j][0], acc[mt][j][1]);
                *(float2*)(p1 + j * 8) = make_float2(acc[mt][j][2], acc[mt][j][3]);
            }
        }
    }
}

extern "C" void kernel_launch(void* const* d_in, const int* in_sizes, int n_in,
                              void* d_out, int out_size) {
    const float* x           = (const float*)d_in[0];
    const int*   var_idx     = (const int*)d_in[1];
    const float* core        = (const float*)d_in[2];
    const float* factor_vars = (const float*)d_in[3];
    const float* fac_in      = (const float*)d_in[4];
    const float* fac_out     = (const float*)d_in[5];
    float* out = (float*)d_out;

    precompute_kernel<<<BV, 256>>>(var_idx, core, factor_vars, fac_in, fac_out);

    dim3 grid(ROWS_PER_BV / Mq, BV);   // (512, 16)
    tucker_mma_kernel<<<grid, TPB>>>(x, out);
}